// round 6
// baseline (speedup 1.0000x reference)
#include <cuda_runtime.h>

// CharRNN: 3-layer tanh RNN, B=512, T=1024, HID=100, VOCAB=62.
// R6: layer-pipelined ticks (L1(t),L2(t-1),L3(t-2),DEC(t-3) concurrent),
//     ONE barrier/tick, 640 threads (20 warps), lane=(row,j2) owns 2 j's,
//     weights full-width LDS (128B/slot), h one slot for all 4 rows,
//     Wdec packed in gmem (prologue repack), double-buffered h.

#define BB    512
#define TT    1024
#define HID   100
#define VOCAB 62
#define NL    3
#define ROWS  4
#define NCTA  (BB / ROWS)       // 128
#define NTHR  640               // 20 warps

// ---- shared memory layout (floats) ----
#define OFF_WH1  0
#define OFF_WI2  10000
#define OFF_WH2  20000
#define OFF_WI3  30000
#define OFF_WH3  40000
#define OFF_H    50000          // [2 buf][3 layer][4 rows][100]
#define SMEM_FLOATS (OFF_H + 2 * NL * ROWS * HID)   // 52,400 -> 209,600 B

typedef unsigned long long ull;

__device__ float  g_table[VOCAB * HID];     // emb@Wi1^T + b_ih1 + b_hh1
__device__ float4 g_wdec[4 * 25 * 16];      // packed Wdec: [jb][kc][jl] quads

// ---------------------------------------------------------------------------
__global__ void table_kernel(const float* __restrict__ emb,
                             const float* __restrict__ W_ih,
                             const float* __restrict__ b_ih,
                             const float* __restrict__ b_hh) {
    int v = blockIdx.x;
    int j = threadIdx.x;
    if (j >= HID) return;
    float acc = b_ih[j] + b_hh[j];
    const float* e = emb + v * HID;
    const float* w = W_ih + j * HID;
#pragma unroll
    for (int k = 0; k < HID; k++) acc += e[k] * w[k];
    g_table[v * HID + j] = acc;
}

__global__ void pack_dec_kernel(const float* __restrict__ W_dec) {
    int i = blockIdx.x * blockDim.x + threadIdx.x;
    if (i >= 4 * 25 * 16) return;
    int jb  = i / 400;
    int rem = i - jb * 400;
    int kc  = rem >> 4;
    int jl  = rem & 15;
    int j   = jb * 16 + jl;
    float4 v = make_float4(0.f, 0.f, 0.f, 0.f);
    if (j < VOCAB) v = *reinterpret_cast<const float4*>(W_dec + j * HID + kc * 4);
    g_wdec[i] = v;
}

// ---------------------------------------------------------------------------
__device__ __forceinline__ void fma2(ull& acc, ull a, ull b) {
    asm("fma.rn.f32x2 %0, %1, %2, %3;" : "=l"(acc) : "l"(a), "l"(b), "l"(acc));
}
__device__ __forceinline__ float hadd2(ull a) {
    float lo = __uint_as_float((unsigned)a);
    float hi = __uint_as_float((unsigned)(a >> 32));
    return lo + hi;
}
__device__ __forceinline__ ulonglong2 ldv(const float* pf) {
    return *reinterpret_cast<const ulonglong2*>(pf);
}
__device__ __forceinline__ float tanho(float x) {
    float e = __expf(2.0f * x);
    return 1.0f - __fdividef(2.0f, e + 1.0f);
}

// ---------------------------------------------------------------------------
__global__ __launch_bounds__(NTHR, 1)
void rnn_kernel(const int*   __restrict__ ids,
                const float* __restrict__ W_ih,
                const float* __restrict__ W_hh,
                const float* __restrict__ b_ih,
                const float* __restrict__ b_hh,
                const float* __restrict__ b_dec,
                float* __restrict__ logits,
                float* __restrict__ hidden) {
    extern __shared__ float s[];
    const int tid  = threadIdx.x;
    const int wid  = tid >> 5;
    const int lane = tid & 31;
    const int row  = lane >> 3;       // 0..3 : batch row
    const int j2   = lane & 7;        // 0..7 : j sub-slot
    const int b0   = blockIdx.x * ROWS;

    // ---- stage weights ----
    for (int i = tid; i < HID * HID; i += NTHR) {
        s[OFF_WH1 + i] = W_hh[i];
        s[OFF_WI2 + i] = W_ih[1 * HID * HID + i];
        s[OFF_WH2 + i] = W_hh[1 * HID * HID + i];
        s[OFF_WI3 + i] = W_ih[2 * HID * HID + i];
        s[OFF_WH3 + i] = W_hh[2 * HID * HID + i];
    }
    for (int i = tid; i < 2 * NL * ROWS * HID; i += NTHR) s[OFF_H + i] = 0.0f;

    // ---- per-warp role setup ----
    // warps 0-6  : L2 heavy  (t = u-1), jbase = wid*16
    // warps 7-13 : L3 heavy  (t = u-2), jbase = (wid-7)*16
    // warps 14-19: two light jobs from list: 7x L1 (t=u), 4x DEC (t=u-3)
    int  jA = 0, jB = 0, jAc = 0, jBc = 0;
    int  wiA = 0, whA = 0, wiB = 0, whB = 0;   // smem float offsets
    float bA = 0.f, bB = 0.f;
    int  jt[2]  = {-1, -1};
    int  ljA[2], ljB[2], ljAc[2], ljBc[2], lwA[2], lwB[2], lpA[2], lpB[2];
    float lbA[2], lbB[2];
    bool hasL1 = false;

    if (wid < 14) {
        const int l   = (wid < 7) ? 1 : 2;          // layer index
        const int jb  = (wid < 7 ? wid : wid - 7) * 16;
        jA  = jb + j2;       jB  = jA + 8;
        jAc = jA < HID ? jA : HID - 1;
        jBc = jB < HID ? jB : HID - 1;
        const int OWI = (l == 1) ? OFF_WI2 : OFF_WI3;
        const int OWH = (l == 1) ? OFF_WH2 : OFF_WH3;
        wiA = OWI + jAc * HID;  whA = OWH + jAc * HID;
        wiB = OWI + jBc * HID;  whB = OWH + jBc * HID;
        bA = b_ih[l * HID + jAc] + b_hh[l * HID + jAc];
        bB = b_ih[l * HID + jBc] + b_hh[l * HID + jBc];
    } else {
        const int lw = wid - 14;
#pragma unroll
        for (int q = 0; q < 2; q++) {
            const int ji = lw * 2 + q;
            if (ji >= 11) { jt[q] = -1; continue; }
            if (ji < 7) {                       // L1 job
                jt[q] = 0; hasL1 = true;
                const int jb = ji * 16;
                ljA[q] = jb + j2;  ljB[q] = ljA[q] + 8;
                ljAc[q] = ljA[q] < HID ? ljA[q] : HID - 1;
                ljBc[q] = ljB[q] < HID ? ljB[q] : HID - 1;
                lwA[q] = OFF_WH1 + ljAc[q] * HID;
                lwB[q] = OFF_WH1 + ljBc[q] * HID;
                lbA[q] = 0.f; lbB[q] = 0.f; lpA[q] = 0; lpB[q] = 0;
            } else {                            // DEC job
                jt[q] = 1;
                const int jbi = ji - 7;
                const int jb  = jbi * 16;
                ljA[q] = jb + j2;  ljB[q] = ljA[q] + 8;
                lpA[q] = jbi * 400 + j2;        // packed quad index (+ kc*16)
                lpB[q] = lpA[q] + 8;
                lbA[q] = b_dec[ljA[q] < VOCAB ? ljA[q] : VOCAB - 1];
                lbB[q] = b_dec[ljB[q] < VOCAB ? ljB[q] : VOCAB - 1];
                lwA[q] = 0; lwB[q] = 0; ljAc[q] = 0; ljBc[q] = 0;
            }
        }
    }
    __syncthreads();

    // ======================= pipelined tick loop =======================
    for (int u = 0; u < TT + 3; u++) {
        const int wb = u & 1;
        const float* hr = s + OFF_H + (wb ^ 1) * (NL * ROWS * HID);
        float*       hw = s + OFF_H + wb * (NL * ROWS * HID);

        if (wid < 7) {
            // ---- L2: t = u-1 ----
            if (u >= 1 && u <= TT) {
                const float* h1p = hr + 0 * 400 + row * HID;
                const float* h2p = hr + 1 * 400 + row * HID;
                ull aA = 0, aB = 0;
#pragma unroll
                for (int kc = 0; kc < 25; kc++) {
                    ulonglong2 h1 = ldv(h1p + 4 * kc);
                    ulonglong2 h2 = ldv(h2p + 4 * kc);
                    ulonglong2 wa = ldv(s + wiA + 4 * kc);
                    ulonglong2 wb2 = ldv(s + whA + 4 * kc);
                    ulonglong2 wc = ldv(s + wiB + 4 * kc);
                    ulonglong2 wd = ldv(s + whB + 4 * kc);
                    fma2(aA, wa.x, h1.x); fma2(aA, wa.y, h1.y);
                    fma2(aA, wb2.x, h2.x); fma2(aA, wb2.y, h2.y);
                    fma2(aB, wc.x, h1.x); fma2(aB, wc.y, h1.y);
                    fma2(aB, wd.x, h2.x); fma2(aB, wd.y, h2.y);
                }
                float vA = hadd2(aA), vB = hadd2(aB);
                if (jA < HID) hw[1 * 400 + row * HID + jA] = tanho(bA + vA);
                if (jB < HID) hw[1 * 400 + row * HID + jB] = tanho(bB + vB);
            }
        } else if (wid < 14) {
            // ---- L3: t = u-2 ----
            if (u >= 2 && u <= TT + 1) {
                const float* h2p = hr + 1 * 400 + row * HID;
                const float* h3p = hr + 2 * 400 + row * HID;
                ull aA = 0, aB = 0;
#pragma unroll
                for (int kc = 0; kc < 25; kc++) {
                    ulonglong2 h2 = ldv(h2p + 4 * kc);
                    ulonglong2 h3 = ldv(h3p + 4 * kc);
                    ulonglong2 wa = ldv(s + wiA + 4 * kc);
                    ulonglong2 wb2 = ldv(s + whA + 4 * kc);
                    ulonglong2 wc = ldv(s + wiB + 4 * kc);
                    ulonglong2 wd = ldv(s + whB + 4 * kc);
                    fma2(aA, wa.x, h2.x); fma2(aA, wa.y, h2.y);
                    fma2(aA, wb2.x, h3.x); fma2(aA, wb2.y, h3.y);
                    fma2(aB, wc.x, h2.x); fma2(aB, wc.y, h2.y);
                    fma2(aB, wd.x, h3.x); fma2(aB, wd.y, h3.y);
                }
                float vA = hadd2(aA), vB = hadd2(aB);
                if (jA < HID) hw[2 * 400 + row * HID + jA] = tanho(bA + vA);
                if (jB < HID) hw[2 * 400 + row * HID + jB] = tanho(bB + vB);
            }
        } else {
            // ---- light warps: up to 2 jobs (L1 t=u, DEC t=u-3) ----
            int   tok = 0;
            if (hasL1 && u < TT) tok = ids[(b0 + row) * TT + u];
#pragma unroll
            for (int q = 0; q < 2; q++) {
                if (jt[q] == 0) {
                    if (u < TT) {
                        float tA = g_table[tok * HID + ljAc[q]];
                        float tB = g_table[tok * HID + ljBc[q]];
                        const float* h1p = hr + 0 * 400 + row * HID;
                        ull aA = 0, aB = 0;
#pragma unroll
                        for (int kc = 0; kc < 25; kc++) {
                            ulonglong2 h1 = ldv(h1p + 4 * kc);
                            ulonglong2 wa = ldv(s + lwA[q] + 4 * kc);
                            ulonglong2 wc = ldv(s + lwB[q] + 4 * kc);
                            fma2(aA, wa.x, h1.x); fma2(aA, wa.y, h1.y);
                            fma2(aB, wc.x, h1.x); fma2(aB, wc.y, h1.y);
                        }
                        float vA = hadd2(aA), vB = hadd2(aB);
                        if (ljA[q] < HID) hw[0 * 400 + row * HID + ljA[q]] = tanho(tA + vA);
                        if (ljB[q] < HID) hw[0 * 400 + row * HID + ljB[q]] = tanho(tB + vB);
                    }
                } else if (jt[q] == 1) {
                    if (u >= 3) {
                        const int t = u - 3;
                        const float* h3p = hr + 2 * 400 + row * HID;
                        ull aA = 0, aB = 0;
#pragma unroll
                        for (int kc = 0; kc < 25; kc++) {
                            ulonglong2 h3 = ldv(h3p + 4 * kc);
                            ulonglong2 wa = *reinterpret_cast<const ulonglong2*>(&g_wdec[lpA[q] + kc * 16]);
                            ulonglong2 wc = *reinterpret_cast<const ulonglong2*>(&g_wdec[lpB[q] + kc * 16]);
                            fma2(aA, wa.x, h3.x); fma2(aA, wa.y, h3.y);
                            fma2(aB, wc.x, h3.x); fma2(aB, wc.y, h3.y);
                        }
                        float vA = hadd2(aA), vB = hadd2(aB);
                        if (ljA[q] < VOCAB)
                            logits[((size_t)(b0 + row) * TT + t) * VOCAB + ljA[q]] = lbA[q] + vA;
                        if (ljB[q] < VOCAB)
                            logits[((size_t)(b0 + row) * TT + t) * VOCAB + ljB[q]] = lbB[q] + vB;
                    }
                }
            }
        }
        __syncthreads();
    }

    // ---- final hidden [NL, B, HID]: h1 in buf1, h2 in buf0, h3 in buf1 ----
    for (int i = tid; i < NL * ROWS * HID; i += NTHR) {
        const int l = i / (ROWS * HID);
        const int rj = i - l * (ROWS * HID);
        const int r = rj / HID;
        const int j = rj - r * HID;
        const int buf = (l == 1) ? 0 : 1;
        hidden[(size_t)(l * BB + b0 + r) * HID + j] =
            s[OFF_H + (buf * NL + l) * 400 + r * HID + j];
    }
}

// ---------------------------------------------------------------------------
extern "C" void kernel_launch(void* const* d_in, const int* in_sizes, int n_in,
                              void* d_out, int out_size) {
    const int*   ids   = (const int*)  d_in[0];
    const float* emb   = (const float*)d_in[1];
    const float* W_ih  = (const float*)d_in[2];
    const float* W_hh  = (const float*)d_in[3];
    const float* b_ih  = (const float*)d_in[4];
    const float* b_hh  = (const float*)d_in[5];
    const float* W_dec = (const float*)d_in[6];
    const float* b_dec = (const float*)d_in[7];

    float* out    = (float*)d_out;
    float* logits = out;
    float* hidden = out + ((size_t)out_size - (size_t)NL * BB * HID);

    table_kernel<<<VOCAB, 128>>>(emb, W_ih, b_ih, b_hh);
    pack_dec_kernel<<<7, 256>>>(W_dec);

    size_t smem = SMEM_FLOATS * sizeof(float);
    cudaFuncSetAttribute(rnn_kernel, cudaFuncAttributeMaxDynamicSharedMemorySize,
                         (int)smem);
    rnn_kernel<<<NCTA, NTHR, smem>>>(ids, W_ih, W_hh, b_ih, b_hh,
                                     b_dec, logits, hidden);
}

// round 7
// speedup vs baseline: 1.5285x; 1.5285x over previous
#include <cuda_runtime.h>

// CharRNN: 3-layer tanh RNN, B=512, T=1024, HID=100, VOCAB=62.
// R7: R4's 3-phase/3-barrier structure WITHOUT the spill cause:
//     - no per-thread weight register arrays (R4's regs=230 spill bug)
//     - Wh1..Wh3 all in smem; W_dec read from gmem (L1-resident) in phase A
//     - in-warp 2-way k-split (m=lane>>1, p=lane&1), shfl_xor(1) reduction
//     - dec(t-1) merged with L1(t); double-buffered h; fast tanh.

#define BB    512
#define TT    1024
#define HID   100
#define VOCAB 62
#define NL    3
#define ROWS  4
#define NCTA  (BB / ROWS)       // 128
#define NTHR  256

// ---- shared memory layout (floats) ----
#define OFF_WH1  0
#define OFF_WI2  10000
#define OFF_WH2  20000
#define OFF_WI3  30000
#define OFF_WH3  40000
#define OFF_H    50000          // [2 buf][NL][ROWS][HID]
#define SMEM_FLOATS (OFF_H + 2 * NL * ROWS * HID)   // 52,400 -> 209,600 B

typedef unsigned long long ull;

__device__ float g_table[VOCAB * HID];  // emb@Wi1^T + b_ih1 + b_hh1

// ---------------------------------------------------------------------------
__global__ void table_kernel(const float* __restrict__ emb,
                             const float* __restrict__ W_ih,
                             const float* __restrict__ b_ih,
                             const float* __restrict__ b_hh) {
    int v = blockIdx.x;
    int j = threadIdx.x;
    if (j >= HID) return;
    float acc = b_ih[j] + b_hh[j];
    const float* e = emb + v * HID;
    const float* w = W_ih + j * HID;
#pragma unroll
    for (int k = 0; k < HID; k++) acc += e[k] * w[k];
    g_table[v * HID + j] = acc;
}

// ---------------------------------------------------------------------------
__device__ __forceinline__ void fma2(ull& acc, ull a, ull b) {
    asm("fma.rn.f32x2 %0, %1, %2, %3;" : "=l"(acc) : "l"(a), "l"(b), "l"(acc));
}
__device__ __forceinline__ float hadd2(ull a) {
    float lo = __uint_as_float((unsigned)a);
    float hi = __uint_as_float((unsigned)(a >> 32));
    return lo + hi;
}
__device__ __forceinline__ ulonglong2 ldv(const float* pf) {
    return *reinterpret_cast<const ulonglong2*>(pf);
}
__device__ __forceinline__ float tanho(float x) {
    float e = __expf(2.0f * x);
    return 1.0f - __fdividef(2.0f, e + 1.0f);
}
__device__ __forceinline__ float red2(ull a) {     // k-half pair reduction
    float v = hadd2(a);
    v += __shfl_xor_sync(0xffffffffu, v, 1);
    return v;
}

// ---------------------------------------------------------------------------
__global__ __launch_bounds__(NTHR, 1)
void rnn_kernel(const int*   __restrict__ ids,
                const float* __restrict__ W_ih,
                const float* __restrict__ W_hh,
                const float* __restrict__ b_ih,
                const float* __restrict__ b_hh,
                const float* __restrict__ W_dec,
                const float* __restrict__ b_dec,
                float* __restrict__ logits,
                float* __restrict__ hidden) {
    extern __shared__ float s[];
    const int tid  = threadIdx.x;
    const int wid  = tid >> 5;
    const int lane = tid & 31;
    const int m    = lane >> 1;        // neuron slot within warp (0..15)
    const int p    = lane & 1;         // k-half: 0 -> [0,52), 1 -> [52,100)
    const int b0   = blockIdx.x * ROWS;
    const int kh   = p * 52;

    const int  j1    = wid * 13 + m;                 // layer neuron
    const int  j1c   = (j1 < HID) ? j1 : (HID - 1);
    const bool w1act = (p == 0) && (m < 13) && (j1 < HID);
    const int  jd    = wid * 8 + m;                  // decoder neuron
    const int  jdc   = (jd < VOCAB) ? jd : (VOCAB - 1);
    const bool wdact = (p == 0) && (m < 8) && (jd < VOCAB);

    // ---- stage weights into smem ----
    for (int i = tid; i < HID * HID; i += NTHR) {
        s[OFF_WH1 + i] = W_hh[i];
        s[OFF_WI2 + i] = W_ih[1 * HID * HID + i];
        s[OFF_WH2 + i] = W_hh[1 * HID * HID + i];
        s[OFF_WI3 + i] = W_ih[2 * HID * HID + i];
        s[OFF_WH3 + i] = W_hh[2 * HID * HID + i];
    }
    for (int i = tid; i < 2 * NL * ROWS * HID; i += NTHR) s[OFF_H + i] = 0.0f;

    const float b2r = b_ih[1 * HID + j1c] + b_hh[1 * HID + j1c];
    const float b3r = b_ih[2 * HID + j1c] + b_hh[2 * HID + j1c];
    const float bdr = b_dec[jdc];

    const float* wh1row = s + OFF_WH1 + j1c * HID + kh;
    const float* wi2row = s + OFF_WI2 + j1c * HID + kh;
    const float* wh2row = s + OFF_WH2 + j1c * HID + kh;
    const float* wi3row = s + OFF_WI3 + j1c * HID + kh;
    const float* wh3row = s + OFF_WH3 + j1c * HID + kh;
    const float* wdrow  = W_dec + jdc * HID + kh;    // gmem, L1-resident

    int tok[ROWS];
#pragma unroll
    for (int r = 0; r < ROWS; r++) tok[r] = ids[(b0 + r) * TT];

    __syncthreads();

    for (int t = 0; t < TT; t++) {
        const int ro = t & 1, wo = ro ^ 1;
        const float* h1o = s + OFF_H + (ro * NL + 0) * ROWS * HID;
        const float* h2o = s + OFF_H + (ro * NL + 1) * ROWS * HID;
        const float* h3o = s + OFF_H + (ro * NL + 2) * ROWS * HID;
        float* h1n = s + OFF_H + (wo * NL + 0) * ROWS * HID;
        float* h2n = s + OFF_H + (wo * NL + 1) * ROWS * HID;
        float* h3n = s + OFF_H + (wo * NL + 2) * ROWS * HID;

        // ========= phase A: layer-1(t) + decoder(t-1) =========
        {
            float tbl[ROWS];
#pragma unroll
            for (int r = 0; r < ROWS; r++) tbl[r] = g_table[tok[r] * HID + j1c];

            ull a1[ROWS] = {0, 0, 0, 0};
            ull ad[ROWS] = {0, 0, 0, 0};
#pragma unroll
            for (int kc = 0; kc < 12; kc++) {
                ulonglong2 w1 = ldv(wh1row + 4 * kc);
                ulonglong2 wd = ldv(wdrow + 4 * kc);
#pragma unroll
                for (int r = 0; r < ROWS; r++) {
                    ulonglong2 h1 = ldv(h1o + r * HID + kh + 4 * kc);
                    ulonglong2 h3 = ldv(h3o + r * HID + kh + 4 * kc);
                    fma2(a1[r], w1.x, h1.x); fma2(a1[r], w1.y, h1.y);
                    fma2(ad[r], wd.x, h3.x); fma2(ad[r], wd.y, h3.y);
                }
            }
            if (p == 0) {   // 13th quad, lo half only
                ulonglong2 w1 = ldv(wh1row + 48);
                ulonglong2 wd = ldv(wdrow + 48);
#pragma unroll
                for (int r = 0; r < ROWS; r++) {
                    ulonglong2 h1 = ldv(h1o + r * HID + kh + 48);
                    ulonglong2 h3 = ldv(h3o + r * HID + kh + 48);
                    fma2(a1[r], w1.x, h1.x); fma2(a1[r], w1.y, h1.y);
                    fma2(ad[r], wd.x, h3.x); fma2(ad[r], wd.y, h3.y);
                }
            }
#pragma unroll
            for (int r = 0; r < ROWS; r++) {
                float s1 = red2(a1[r]);
                float sd = red2(ad[r]);
                if (w1act) h1n[r * HID + j1] = tanho(tbl[r] + s1);
                if (wdact && t > 0)
                    logits[((size_t)(b0 + r) * TT + (t - 1)) * VOCAB + jd] = bdr + sd;
            }
        }
        __syncthreads();

        // ========= phase B: layer-2 =========
        {
            ull a[ROWS] = {0, 0, 0, 0};
#pragma unroll
            for (int kc = 0; kc < 12; kc++) {
                ulonglong2 wi = ldv(wi2row + 4 * kc);
                ulonglong2 wh = ldv(wh2row + 4 * kc);
#pragma unroll
                for (int r = 0; r < ROWS; r++) {
                    ulonglong2 hx = ldv(h1n + r * HID + kh + 4 * kc);
                    ulonglong2 hh = ldv(h2o + r * HID + kh + 4 * kc);
                    fma2(a[r], wi.x, hx.x); fma2(a[r], wi.y, hx.y);
                    fma2(a[r], wh.x, hh.x); fma2(a[r], wh.y, hh.y);
                }
            }
            if (p == 0) {
                ulonglong2 wi = ldv(wi2row + 48);
                ulonglong2 wh = ldv(wh2row + 48);
#pragma unroll
                for (int r = 0; r < ROWS; r++) {
                    ulonglong2 hx = ldv(h1n + r * HID + kh + 48);
                    ulonglong2 hh = ldv(h2o + r * HID + kh + 48);
                    fma2(a[r], wi.x, hx.x); fma2(a[r], wi.y, hx.y);
                    fma2(a[r], wh.x, hh.x); fma2(a[r], wh.y, hh.y);
                }
            }
#pragma unroll
            for (int r = 0; r < ROWS; r++) {
                float sv = red2(a[r]);
                if (w1act) h2n[r * HID + j1] = tanho(b2r + sv);
            }
        }
        __syncthreads();

        // ========= phase C: layer-3 + next-token prefetch =========
        {
            const int tn = (t + 1 < TT) ? (t + 1) : t;
#pragma unroll
            for (int r = 0; r < ROWS; r++) tok[r] = ids[(b0 + r) * TT + tn];

            ull a[ROWS] = {0, 0, 0, 0};
#pragma unroll
            for (int kc = 0; kc < 12; kc++) {
                ulonglong2 wi = ldv(wi3row + 4 * kc);
                ulonglong2 wh = ldv(wh3row + 4 * kc);
#pragma unroll
                for (int r = 0; r < ROWS; r++) {
                    ulonglong2 hx = ldv(h2n + r * HID + kh + 4 * kc);
                    ulonglong2 hh = ldv(h3o + r * HID + kh + 4 * kc);
                    fma2(a[r], wi.x, hx.x); fma2(a[r], wi.y, hx.y);
                    fma2(a[r], wh.x, hh.x); fma2(a[r], wh.y, hh.y);
                }
            }
            if (p == 0) {
                ulonglong2 wi = ldv(wi3row + 48);
                ulonglong2 wh = ldv(wh3row + 48);
#pragma unroll
                for (int r = 0; r < ROWS; r++) {
                    ulonglong2 hx = ldv(h2n + r * HID + kh + 48);
                    ulonglong2 hh = ldv(h3o + r * HID + kh + 48);
                    fma2(a[r], wi.x, hx.x); fma2(a[r], wi.y, hx.y);
                    fma2(a[r], wh.x, hh.x); fma2(a[r], wh.y, hh.y);
                }
            }
#pragma unroll
            for (int r = 0; r < ROWS; r++) {
                float sv = red2(a[r]);
                if (w1act) h3n[r * HID + j1] = tanho(b3r + sv);
            }
        }
        __syncthreads();
    }

    // ---- final decoder for t = TT-1 (final h lives in buffer 0) ----
    {
        const float* h3f = s + OFF_H + (0 * NL + 2) * ROWS * HID;
        ull ad[ROWS] = {0, 0, 0, 0};
#pragma unroll
        for (int kc = 0; kc < 12; kc++) {
            ulonglong2 wd = ldv(wdrow + 4 * kc);
#pragma unroll
            for (int r = 0; r < ROWS; r++) {
                ulonglong2 h3 = ldv(h3f + r * HID + kh + 4 * kc);
                fma2(ad[r], wd.x, h3.x); fma2(ad[r], wd.y, h3.y);
            }
        }
        if (p == 0) {
            ulonglong2 wd = ldv(wdrow + 48);
#pragma unroll
            for (int r = 0; r < ROWS; r++) {
                ulonglong2 h3 = ldv(h3f + r * HID + kh + 48);
                fma2(ad[r], wd.x, h3.x); fma2(ad[r], wd.y, h3.y);
            }
        }
#pragma unroll
        for (int r = 0; r < ROWS; r++) {
            float sd = red2(ad[r]);
            if (wdact)
                logits[((size_t)(b0 + r) * TT + (TT - 1)) * VOCAB + jd] = bdr + sd;
        }
    }

    // ---- final hidden states [NL, B, HID] (buffer 0) ----
    if (w1act) {
#pragma unroll
        for (int l = 0; l < NL; l++) {
            const float* hf = s + OFF_H + (0 * NL + l) * ROWS * HID;
#pragma unroll
            for (int r = 0; r < ROWS; r++)
                hidden[(size_t)(l * BB + b0 + r) * HID + j1] = hf[r * HID + j1];
        }
    }
}

// ---------------------------------------------------------------------------
extern "C" void kernel_launch(void* const* d_in, const int* in_sizes, int n_in,
                              void* d_out, int out_size) {
    const int*   ids   = (const int*)  d_in[0];
    const float* emb   = (const float*)d_in[1];
    const float* W_ih  = (const float*)d_in[2];
    const float* W_hh  = (const float*)d_in[3];
    const float* b_ih  = (const float*)d_in[4];
    const float* b_hh  = (const float*)d_in[5];
    const float* W_dec = (const float*)d_in[6];
    const float* b_dec = (const float*)d_in[7];

    float* out    = (float*)d_out;
    float* logits = out;
    float* hidden = out + ((size_t)out_size - (size_t)NL * BB * HID);

    table_kernel<<<VOCAB, 128>>>(emb, W_ih, b_ih, b_hh);

    size_t smem = SMEM_FLOATS * sizeof(float);
    cudaFuncSetAttribute(rnn_kernel, cudaFuncAttributeMaxDynamicSharedMemorySize,
                         (int)smem);
    rnn_kernel<<<NCTA, NTHR, smem>>>(ids, W_ih, W_hh, b_ih, b_hh,
                                     W_dec, b_dec, logits, hidden);
}

// round 8
// speedup vs baseline: 1.8231x; 1.1928x over previous
#include <cuda_runtime.h>

// CharRNN: 3-layer tanh RNN, B=512, T=1024, HID=100, VOCAB=62.
// R8: (row,j2) lane mapping -> full dots per lane, NO reduction;
//     weight LDS = 1 wf (8 quads x 4-way broadcast), h LDS = 1 wf;
//     decoder offloaded to separate GEMM kernel over a __device__ h3 buffer;
//     2-phase pipeline: P1 = L2(t)+L1(t+1) (shared h1 quad), P2 = L3(t)+STG;
//     2 barriers/step, 224 threads, no per-thread weight arrays.

#define BB    512
#define TT    1024
#define HID   100
#define VOCAB 62
#define NL    3
#define ROWS  4
#define NCTA  (BB / ROWS)       // 128
#define NTHR  224               // 7 warps; 7*16 = 112 j-slots >= 100

// ---- rnn shared memory layout (floats) ----
#define OFF_WH1  0
#define OFF_WI2  10000
#define OFF_WH2  20000
#define OFF_WI3  30000
#define OFF_WH3  40000
#define OFF_H    50000          // [2 buf][NL][ROWS][HID] = 2*1200
#define SMEM_FLOATS (OFF_H + 2 * NL * ROWS * HID)   // 52,400 -> 209,600 B

typedef unsigned long long ull;

__device__ float g_table[VOCAB * HID];                  // emb@Wi1^T + b1
__device__ float g_h3[(size_t)BB * TT * HID];           // h3 stream (200 MB)

// ---------------------------------------------------------------------------
__global__ void table_kernel(const float* __restrict__ emb,
                             const float* __restrict__ W_ih,
                             const float* __restrict__ b_ih,
                             const float* __restrict__ b_hh) {
    int v = blockIdx.x;
    int j = threadIdx.x;
    if (j >= HID) return;
    float acc = b_ih[j] + b_hh[j];
    const float* e = emb + v * HID;
    const float* w = W_ih + j * HID;
#pragma unroll
    for (int k = 0; k < HID; k++) acc += e[k] * w[k];
    g_table[v * HID + j] = acc;
}

// ---------------------------------------------------------------------------
__device__ __forceinline__ void fma2(ull& acc, ull a, ull b) {
    asm("fma.rn.f32x2 %0, %1, %2, %3;" : "=l"(acc) : "l"(a), "l"(b), "l"(acc));
}
__device__ __forceinline__ float hadd2(ull a) {
    float lo = __uint_as_float((unsigned)a);
    float hi = __uint_as_float((unsigned)(a >> 32));
    return lo + hi;
}
__device__ __forceinline__ ulonglong2 ldv(const float* pf) {
    return *reinterpret_cast<const ulonglong2*>(pf);
}
__device__ __forceinline__ float tanho(float x) {
    float e = __expf(2.0f * x);
    return 1.0f - __fdividef(2.0f, e + 1.0f);
}

// ---------------------------------------------------------------------------
__global__ __launch_bounds__(NTHR, 1)
void rnn_kernel(const int*   __restrict__ ids,
                const float* __restrict__ W_ih,
                const float* __restrict__ W_hh,
                const float* __restrict__ b_ih,
                const float* __restrict__ b_hh,
                float* __restrict__ hidden) {
    extern __shared__ float s[];
    const int tid  = threadIdx.x;
    const int wid  = tid >> 5;
    const int lane = tid & 31;
    const int row  = lane >> 3;           // 0..3 batch row
    const int j2   = lane & 7;            // 0..7
    const int b0   = blockIdx.x * ROWS;

    const int jA  = wid * 16 + j2;        // first neuron
    const int jB  = jA + 8;               // second neuron
    const int jAc = (jA < HID) ? jA : (HID - 1);
    const int jBc = (jB < HID) ? jB : (HID - 1);
    const bool wA = (jA < HID);
    const bool wB = (jB < HID);
    const int oA = jAc * HID;
    const int oB = jBc * HID;

    // ---- stage weights ----
    for (int i = tid; i < HID * HID; i += NTHR) {
        s[OFF_WH1 + i] = W_hh[i];
        s[OFF_WI2 + i] = W_ih[1 * HID * HID + i];
        s[OFF_WH2 + i] = W_hh[1 * HID * HID + i];
        s[OFF_WI3 + i] = W_ih[2 * HID * HID + i];
        s[OFF_WH3 + i] = W_hh[2 * HID * HID + i];
    }
    for (int i = tid; i < 2 * NL * ROWS * HID; i += NTHR) s[OFF_H + i] = 0.0f;

    const float b2A = b_ih[1 * HID + jAc] + b_hh[1 * HID + jAc];
    const float b2B = b_ih[1 * HID + jBc] + b_hh[1 * HID + jBc];
    const float b3A = b_ih[2 * HID + jAc] + b_hh[2 * HID + jAc];
    const float b3B = b_ih[2 * HID + jBc] + b_hh[2 * HID + jBc];
    __syncthreads();

    // ---- pre-loop: h1(0) = tanh(table[tok0]) (Wh1 @ 0 = 0) ----
    {
        int tk = ids[(b0 + row) * TT];
        float* h1n = s + OFF_H;           // buf0, layer0
        if (wA) h1n[row * HID + jA] = tanho(g_table[tk * HID + jAc]);
        if (wB) h1n[row * HID + jB] = tanho(g_table[tk * HID + jBc]);
    }
    __syncthreads();

    for (int u = 0; u < TT; u++) {
        const int bu = (u & 1) * 1200, bo = 1200 - bu;

        // ========= P1: L2(u) + L1(u+1) =========
        {
            const float* h1u = s + OFF_H + bu + 0   + row * HID;   // h1(u)
            const float* h2p = s + OFF_H + bo + 400 + row * HID;   // h2(u-1)
            float* h2n = s + OFF_H + bu + 400;                     // h2(u)
            float* h1n = s + OFF_H + bo + 0;                       // h1(u+1)

            const int tn = (u + 1 < TT) ? (u + 1) : (TT - 1);
            const int tk = ids[(b0 + row) * TT + tn];

            ull a2A = 0, a2B = 0, a1A = 0, a1B = 0;
#pragma unroll
            for (int kc = 0; kc < 25; kc++) {
                ulonglong2 h1q = ldv(h1u + 4 * kc);
                ulonglong2 h2q = ldv(h2p + 4 * kc);
                ulonglong2 wiA = ldv(s + OFF_WI2 + oA + 4 * kc);
                ulonglong2 whA = ldv(s + OFF_WH2 + oA + 4 * kc);
                ulonglong2 wiB = ldv(s + OFF_WI2 + oB + 4 * kc);
                ulonglong2 whB = ldv(s + OFF_WH2 + oB + 4 * kc);
                ulonglong2 w1A = ldv(s + OFF_WH1 + oA + 4 * kc);
                ulonglong2 w1B = ldv(s + OFF_WH1 + oB + 4 * kc);
                fma2(a2A, wiA.x, h1q.x); fma2(a2A, wiA.y, h1q.y);
                fma2(a2A, whA.x, h2q.x); fma2(a2A, whA.y, h2q.y);
                fma2(a2B, wiB.x, h1q.x); fma2(a2B, wiB.y, h1q.y);
                fma2(a2B, whB.x, h2q.x); fma2(a2B, whB.y, h2q.y);
                fma2(a1A, w1A.x, h1q.x); fma2(a1A, w1A.y, h1q.y);
                fma2(a1B, w1B.x, h1q.x); fma2(a1B, w1B.y, h1q.y);
            }
            if (wA) h2n[row * HID + jA] = tanho(b2A + hadd2(a2A));
            if (wB) h2n[row * HID + jB] = tanho(b2B + hadd2(a2B));
            if (u + 1 < TT) {
                if (wA) h1n[row * HID + jA] = tanho(g_table[tk * HID + jAc] + hadd2(a1A));
                if (wB) h1n[row * HID + jB] = tanho(g_table[tk * HID + jBc] + hadd2(a1B));
            }
        }
        __syncthreads();

        // ========= P2: L3(u) + h3 stream-out =========
        {
            const float* h2c = s + OFF_H + bu + 400 + row * HID;   // h2(u)
            const float* h3p = s + OFF_H + bo + 800 + row * HID;   // h3(u-1)
            float* h3n = s + OFF_H + bu + 800;                     // h3(u)

            ull a3A = 0, a3B = 0;
#pragma unroll
            for (int kc = 0; kc < 25; kc++) {
                ulonglong2 h2q = ldv(h2c + 4 * kc);
                ulonglong2 h3q = ldv(h3p + 4 * kc);
                ulonglong2 wiA = ldv(s + OFF_WI3 + oA + 4 * kc);
                ulonglong2 whA = ldv(s + OFF_WH3 + oA + 4 * kc);
                ulonglong2 wiB = ldv(s + OFF_WI3 + oB + 4 * kc);
                ulonglong2 whB = ldv(s + OFF_WH3 + oB + 4 * kc);
                fma2(a3A, wiA.x, h2q.x); fma2(a3A, wiA.y, h2q.y);
                fma2(a3A, whA.x, h3q.x); fma2(a3A, whA.y, h3q.y);
                fma2(a3B, wiB.x, h2q.x); fma2(a3B, wiB.y, h2q.y);
                fma2(a3B, whB.x, h3q.x); fma2(a3B, whB.y, h3q.y);
            }
            float* g = g_h3 + ((size_t)(b0 + row) * TT + u) * HID;
            if (wA) {
                float v = tanho(b3A + hadd2(a3A));
                h3n[row * HID + jA] = v;
                g[jA] = v;
            }
            if (wB) {
                float v = tanho(b3B + hadd2(a3B));
                h3n[row * HID + jB] = v;
                g[jB] = v;
            }
        }
        __syncthreads();
    }

    // ---- final hidden [NL, B, HID]: all final states in buf 1 ----
    for (int i = tid; i < NL * ROWS * HID; i += NTHR) {
        const int l = i / (ROWS * HID);
        const int rem = i - l * (ROWS * HID);
        const int r = rem / HID;
        const int j = rem - r * HID;
        hidden[(size_t)(l * BB + b0 + r) * HID + j] = s[OFF_H + 1200 + i];
    }
}

// ---------------------------------------------------------------------------
// Decoder GEMM: logits[bt][v] = b_dec[v] + sum_k g_h3[bt][k] * W_dec[v][k]
// tile = 128 rows; 256 threads: (r = tid&127, half = tid>>7 -> 31 cols each)
// ---------------------------------------------------------------------------
#define DT   256
#define GR   128
#define DS_W 0                       // 6200 floats
#define DS_H 6208                    // 12800 floats (16B aligned)
#define DS_B 19008                   // 62 floats
#define DS_FLOATS 19072              // 76,288 B

__global__ __launch_bounds__(DT)
void dec_kernel(const float* __restrict__ W_dec,
                const float* __restrict__ b_dec,
                float* __restrict__ logits) {
    extern __shared__ float ds[];
    const int tid  = threadIdx.x;
    const int tile = blockIdx.x;

    float4* sw4 = reinterpret_cast<float4*>(ds + DS_W);
    const float4* wsrc = reinterpret_cast<const float4*>(W_dec);
    for (int i = tid; i < VOCAB * HID / 4; i += DT) sw4[i] = wsrc[i];

    float4* sh4 = reinterpret_cast<float4*>(ds + DS_H);
    const float4* hsrc = reinterpret_cast<const float4*>(g_h3 + (size_t)tile * GR * HID);
    for (int i = tid; i < GR * HID / 4; i += DT) sh4[i] = hsrc[i];

    for (int i = tid; i < VOCAB; i += DT) ds[DS_B + i] = b_dec[i];
    __syncthreads();

    const int r    = tid & 127;
    const int half = tid >> 7;
    const int jb   = half * 31;

    ull acc[31];
#pragma unroll
    for (int jj = 0; jj < 31; jj++) acc[jj] = 0ull;

    const float* hrow = ds + DS_H + r * HID;
    for (int kc = 0; kc < 25; kc++) {
        ulonglong2 hq = ldv(hrow + 4 * kc);
#pragma unroll
        for (int jj = 0; jj < 31; jj++) {
            ulonglong2 wq = ldv(ds + DS_W + (jb + jj) * HID + 4 * kc);
            fma2(acc[jj], wq.x, hq.x);
            fma2(acc[jj], wq.y, hq.y);
        }
    }

    float* out = logits + ((size_t)tile * GR + r) * VOCAB + jb;
#pragma unroll
    for (int jj = 0; jj < 31; jj++)
        out[jj] = ds[DS_B + jb + jj] + hadd2(acc[jj]);
}

// ---------------------------------------------------------------------------
extern "C" void kernel_launch(void* const* d_in, const int* in_sizes, int n_in,
                              void* d_out, int out_size) {
    const int*   ids   = (const int*)  d_in[0];
    const float* emb   = (const float*)d_in[1];
    const float* W_ih  = (const float*)d_in[2];
    const float* W_hh  = (const float*)d_in[3];
    const float* b_ih  = (const float*)d_in[4];
    const float* b_hh  = (const float*)d_in[5];
    const float* W_dec = (const float*)d_in[6];
    const float* b_dec = (const float*)d_in[7];

    float* out    = (float*)d_out;
    float* logits = out;
    float* hidden = out + ((size_t)out_size - (size_t)NL * BB * HID);

    table_kernel<<<VOCAB, 128>>>(emb, W_ih, b_ih, b_hh);

    size_t smem = SMEM_FLOATS * sizeof(float);
    cudaFuncSetAttribute(rnn_kernel, cudaFuncAttributeMaxDynamicSharedMemorySize,
                         (int)smem);
    rnn_kernel<<<NCTA, NTHR, smem>>>(ids, W_ih, W_hh, b_ih, b_hh, hidden);

    size_t dsmem = DS_FLOATS * sizeof(float);
    cudaFuncSetAttribute(dec_kernel, cudaFuncAttributeMaxDynamicSharedMemorySize,
                         (int)dsmem);
    dec_kernel<<<(BB * TT) / GR, DT, dsmem>>>(W_dec, b_dec, logits);
}